// round 13
// baseline (speedup 1.0000x reference)
#include <cuda_runtime.h>
#include <math.h>

// Problem constants
#define N_CAPS 64
#define CAPS_DIM 16
#define OUT_DIM 128
#define P_DIM 1152
#define BATCH 256
#define BO (BATCH * OUT_DIM)       // 32768
#define BO4 (BO / 4)               // 8192 float4 per p-row
#define WROW 132                   // padded row stride (float4-aligned)

#define THREADS 512
#define NBLK 296                   // 148 SMs x 2 co-resident blocks: ONE wave
#define NCH 8                      // P chunks per batch
#define PCH (P_DIM / NCH)          // 144 rows per item
#define ITEMS (BATCH * NCH)        // 2048 work items

// Scratch (no cudaMalloc allowed)
__device__ __align__(16) float g_part[BATCH * NCH * OUT_DIM];  // 1 MB
__device__ __align__(16) float g_wsum[N_CAPS * OUT_DIM];       // 32 KB
__device__ int g_qhead;           // work queue head
__device__ int g_done[BATCH];     // per-batch completed chunks
__device__ int g_wflag;           // wsum ready (target 4)
__device__ int g_exit;            // blocks exited -> last one resets all

// ---------------------------------------------------------------------------
// Persistent fused kernel: 296 blocks x 512 threads, all co-resident.
//  bids 0..3 first compute a Wsum slice, then everyone pulls stream items
//  (b, chunk) off an atomic queue. The block that completes a batch's 8th
//  chunk runs that batch's routing epilogue inline (overlapped with other
//  blocks' streaming). Counters self-reset for graph replay.
// ---------------------------------------------------------------------------
__global__ void __launch_bounds__(THREADS, 2) capsule_fused(
    const float4* __restrict__ x4,        // (1152, 256, 128) fp32
    const float4* __restrict__ w4,        // (64, 16, 128) fp32
    float* __restrict__ out)              // (256, 1, 128)
{
    const int bid  = blockIdx.x;
    const int t    = threadIdx.x;
    const int g    = t >> 5;      // warp id 0..15
    const int lane = t & 31;

    __shared__ __align__(16) float sh_red[16][OUT_DIM];   // 8 KB
    __shared__ __align__(16) float sh_w[N_CAPS * WROW];   // 33.8 KB
    __shared__ __align__(16) float shrp0[OUT_DIM];
    __shared__ float shpart[128];
    __shared__ float shc[N_CAPS];
    __shared__ float shred[4];
    __shared__ int   sh_item, sh_route;

    // ---- wsum prologue (blocks 0..3, one float4 output per thread) ----
    if (bid < 4) {
        int i4 = bid * THREADS + t;                       // 0..2047
        int n  = i4 >> 5;
        int o4 = i4 & 31;
        const float4* base = w4 + (size_t)n * (CAPS_DIM * OUT_DIM / 4) + o4;
        float4 acc = make_float4(0.f, 0.f, 0.f, 0.f);
#pragma unroll
        for (int c = 0; c < CAPS_DIM; ++c) {
            float4 v = __ldg(&base[c * (OUT_DIM / 4)]);
            acc.x += v.x; acc.y += v.y; acc.z += v.z; acc.w += v.w;
        }
        reinterpret_cast<float4*>(g_wsum)[i4] = acc;
        __threadfence();
        __syncthreads();
        if (t == 0) atomicAdd(&g_wflag, 1);
    }

    bool wstaged = false;

    // ---- main work loop ----
    for (;;) {
        if (t == 0) sh_item = atomicAdd(&g_qhead, 1);
        __syncthreads();
        int it = sh_item;
        if (it >= ITEMS) break;

        const int b  = it >> 3;       // batch
        const int ch = it & 7;        // P chunk

        // Stream chunk: warp g reads rows ch*144+g, +16, ... (9 rows)
        {
            const float4* base = x4 + (size_t)(ch * PCH + g) * BO4 + b * 32 + lane;
            float4 acc = make_float4(0.f, 0.f, 0.f, 0.f);
#pragma unroll
            for (int i = 0; i < PCH / 16; ++i) {          // 9 iterations
                float4 v = __ldcs(&base[(size_t)i * 16 * BO4]);
                acc.x += v.x; acc.y += v.y; acc.z += v.z; acc.w += v.w;
            }
            *reinterpret_cast<float4*>(&sh_red[g][lane * 4]) = acc;
        }
        __syncthreads();

        // Combine 16 warp partials -> g_part[b][ch][:]
        if (t < 128) {
            float p = 0.f;
#pragma unroll
            for (int gg = 0; gg < 16; ++gg)
                p += sh_red[gg][t];
            g_part[(b * NCH + ch) * OUT_DIM + t] = p;
            __threadfence();
        }
        __syncthreads();

        if (t == 0) {
            int old = atomicAdd(&g_done[b], 1);
            sh_route = (old == NCH - 1) ? b : -1;
        }
        __syncthreads();
        const int rb = sh_route;
        if (rb < 0) continue;

        // ---- routing epilogue for batch rb ----
        if (!wstaged) {
            if (t == 0) {
                volatile int* f = &g_wflag;
                while (*f < 4) __nanosleep(32);
            }
            __syncthreads();
            __threadfence();
            float4 wv[1];
#pragma unroll
            for (int k = 0; k < 4; ++k) {
                wv[0] = __ldg(&reinterpret_cast<const float4*>(g_wsum)[t + k * THREADS]);
                int i4 = t + k * THREADS;
                int n  = i4 >> 5;
                int o  = (i4 & 31) * 4;
                *reinterpret_cast<float4*>(&sh_w[n * WROW + o]) = wv[0];
            }
            wstaged = true;
        }
        __threadfence();                   // acquire: other blocks' partials

        float X = 0.f;
        if (t < 128) {
#pragma unroll
            for (int c2 = 0; c2 < NCH; ++c2)
                X += g_part[(rb * NCH + c2) * OUT_DIM + t];
        }
        if (t < N_CAPS) shc[t] = 1.0f / N_CAPS;
        float logit_a = 0.f, logit_b = 0.f;
        __syncthreads();

        for (int iter = 0; iter < 3; ++iter) {
            float s = 0.f;
            if (t < 128) {
#pragma unroll
                for (int n = 0; n < N_CAPS; ++n)
                    s += shc[n] * sh_w[n * WROW + t];
                s *= X;
                float sq = s * s;
#pragma unroll
                for (int off = 16; off > 0; off >>= 1)
                    sq += __shfl_xor_sync(0xffffffffu, sq, off);
                if (lane == 0) shred[t >> 5] = sq;
                shrp0[t] = s * X;          // pre-scale routed vector
            }
            __syncthreads();
            float tot   = shred[0] + shred[1] + shred[2] + shred[3];
            float scale = sqrtf(tot) / (1.0f + tot);   // norm/(1+norm^2)

            if (iter == 2) {
                if (t < 128) out[rb * OUT_DIM + t] = scale * s;
                break;
            }

            if (t < 128) {
                int n_id = t & 63, oh = t >> 6;
                const float4* wrow = reinterpret_cast<const float4*>(&sh_w[n_id * WROW]) + oh * 16;
                const float4* rp4  = reinterpret_cast<const float4*>(shrp0) + oh * 16;
                float acc = 0.f;
#pragma unroll
                for (int j = 0; j < 16; ++j) {
                    float4 w4v = wrow[j];
                    float4 r4v = rp4[j];
                    acc += w4v.x * r4v.x + w4v.y * r4v.y + w4v.z * r4v.z + w4v.w * r4v.w;
                }
                shpart[t] = scale * acc;
            }
            __syncthreads();

            if (t < 32) {
                logit_a += shpart[t]      + shpart[t + 64];
                logit_b += shpart[t + 32] + shpart[t + 96];
                float m = fmaxf(logit_a, logit_b);
#pragma unroll
                for (int off = 16; off > 0; off >>= 1)
                    m = fmaxf(m, __shfl_xor_sync(0xffffffffu, m, off));
                float ea = __expf(logit_a - m);
                float eb = __expf(logit_b - m);
                float sm = ea + eb;
#pragma unroll
                for (int off = 16; off > 0; off >>= 1)
                    sm += __shfl_xor_sync(0xffffffffu, sm, off);
                float inv = 1.0f / sm;
                shc[t]      = ea * inv;
                shc[t + 32] = eb * inv;
            }
            __syncthreads();
        }
    }

    // ---- exit + counter reset (graph-replay safe) ----
    if (t == 0) {
        __threadfence();
        int v = atomicAdd(&g_exit, 1);
        if (v == NBLK - 1) {
            g_qhead = 0;
            g_wflag = 0;
            for (int i = 0; i < BATCH; ++i) g_done[i] = 0;
            __threadfence();
            g_exit = 0;
            __threadfence();
        }
    }
}

// ---------------------------------------------------------------------------
extern "C" void kernel_launch(void* const* d_in, const int* in_sizes, int n_in,
                              void* d_out, int out_size) {
    const float* x = (const float*)d_in[0];             // (1152, 256, 128)
    const float* w = (const float*)d_in[1];             // (64, 16, 128)
    float* out = (float*)d_out;                         // (256, 1, 128)

    capsule_fused<<<NBLK, THREADS>>>(reinterpret_cast<const float4*>(x),
                                     reinterpret_cast<const float4*>(w),
                                     out);
}

// round 14
// speedup vs baseline: 1.1837x; 1.1837x over previous
#include <cuda_runtime.h>
#include <math.h>

// Problem constants
#define N_CAPS 64
#define CAPS_DIM 16
#define OUT_DIM 128
#define P_DIM 1152
#define BATCH 256
#define BO (BATCH * OUT_DIM)       // 32768
#define BO4 (BO / 4)               // 8192 float4 per p-row
#define WROW 132                   // padded row stride (float4-aligned)

#define THREADS 1024
#define NB_W 4
#define NB_X 128                   // 2 batch elems per block
#define NBLK (NB_W + NB_X)         // 132 <= 148 SMs: one block per SM
#define ROWS_PER_WARP (P_DIM / 32) // 36

// Scratch (no cudaMalloc allowed)
__device__ __align__(16) float g_wsum[N_CAPS * OUT_DIM];   // 32 KB
__device__ int g_wflag;   // wsum blocks done (target NB_W)
__device__ int g_exit;    // x blocks done -> last one resets wflag

// ---------------------------------------------------------------------------
// Fused kernel, one block per SM (132 blocks, single perfectly-balanced wave).
//  bids 0..3   : Wsum[n,o] = sum_c w[n,c,o]
//  bids 4..131 : stream x[:, b0, :] and x[:, b1, :] with 32 warps (long,
//                barrier-free loops), then run both routing epilogues on
//                warps 0..3 (warps 4..31 exit after staging W).
// ---------------------------------------------------------------------------
__global__ void __launch_bounds__(THREADS, 1) capsule_fused(
    const float4* __restrict__ x4,        // (1152, 256, 128) fp32
    const float4* __restrict__ w4,        // (64, 16, 128) fp32
    float* __restrict__ out)              // (256, 1, 128)
{
    const int bid  = blockIdx.x;
    const int t    = threadIdx.x;
    const int g    = t >> 5;      // warp 0..31
    const int lane = t & 31;

    // ---------------- wsum blocks ----------------
    if (bid < NB_W) {
        int i4 = bid * 512 + t;                          // 0..2047 over 4 blocks
        if (t < 512) {
            int n  = i4 >> 5;
            int o4 = i4 & 31;
            const float4* base = w4 + (size_t)n * (CAPS_DIM * OUT_DIM / 4) + o4;
            float4 acc = make_float4(0.f, 0.f, 0.f, 0.f);
#pragma unroll
            for (int c = 0; c < CAPS_DIM; ++c) {
                float4 v = __ldg(&base[c * (OUT_DIM / 4)]);
                acc.x += v.x; acc.y += v.y; acc.z += v.z; acc.w += v.w;
            }
            reinterpret_cast<float4*>(g_wsum)[i4] = acc;
        }
        __threadfence();
        __syncthreads();
        if (t == 0) atomicAdd(&g_wflag, 1);
        return;
    }

    // ---------------- x blocks ----------------
    const int xb = bid - NB_W;          // 0..127
    const int b0 = xb * 2;
    const int b1 = b0 + 1;

    __shared__ __align__(16) float sh_redA[32][OUT_DIM];  // 16 KB
    __shared__ __align__(16) float sh_redB[32][OUT_DIM];  // 16 KB
    __shared__ __align__(16) float sh_w[N_CAPS * WROW];   // 33.8 KB
    __shared__ __align__(16) float shrp0[OUT_DIM];
    __shared__ float shpart[128];
    __shared__ float shc[N_CAPS];
    __shared__ float shred[4];

    // Stream slice b0: warp g reads rows g, g+32, ... (36 rows, barrier-free)
    {
        const float4* base = x4 + (size_t)g * BO4 + b0 * 32 + lane;
        float4 acc = make_float4(0.f, 0.f, 0.f, 0.f);
#pragma unroll 6
        for (int i = 0; i < ROWS_PER_WARP; ++i) {
            float4 v = __ldcs(&base[(size_t)i * 32 * BO4]);
            acc.x += v.x; acc.y += v.y; acc.z += v.z; acc.w += v.w;
        }
        *reinterpret_cast<float4*>(&sh_redA[g][lane * 4]) = acc;
    }
    // Stream slice b1
    {
        const float4* base = x4 + (size_t)g * BO4 + b1 * 32 + lane;
        float4 acc = make_float4(0.f, 0.f, 0.f, 0.f);
#pragma unroll 6
        for (int i = 0; i < ROWS_PER_WARP; ++i) {
            float4 v = __ldcs(&base[(size_t)i * 32 * BO4]);
            acc.x += v.x; acc.y += v.y; acc.z += v.z; acc.w += v.w;
        }
        *reinterpret_cast<float4*>(&sh_redB[g][lane * 4]) = acc;
    }

    // Wait for wsum (done ~2us in; wsum blocks have their own SMs)
    if (t == 0) {
        volatile int* f = &g_wflag;
        while (*f < NB_W) __nanosleep(32);
    }
    __syncthreads();                 // publishes sh_red* + orders after spin
    __threadfence();

    // Stage W into padded shared (1024 threads, 2 float4 each, batched)
    {
        const float4* gw4 = reinterpret_cast<const float4*>(g_wsum);
        float4 wv0 = __ldg(&gw4[t]);
        float4 wv1 = __ldg(&gw4[t + 1024]);
        int n0 = t >> 5,            o0 = (t & 31) * 4;
        int n1 = (t + 1024) >> 5,   o1 = (t & 31) * 4;
        *reinterpret_cast<float4*>(&sh_w[n0 * WROW + o0]) = wv0;
        *reinterpret_cast<float4*>(&sh_w[n1 * WROW + o1]) = wv1;
    }
    __syncthreads();

    // Exit bookkeeping on a departing warp; reset is safe: every block
    // increments only after passing its own wflag wait.
    if (t == 512) {
        __threadfence();
        int v = atomicAdd(&g_exit, 1);
        if (v == NB_X - 1) {
            g_wflag = 0;
            __threadfence();
            g_exit = 0;
            __threadfence();
        }
    }
    if (g >= 4) return;              // epilogues run on 4 warps

    // ---------------- two routing epilogues (b0 then b1) ----------------
#pragma unroll 1
    for (int eb = 0; eb < 2; ++eb) {
        const int b = (eb == 0) ? b0 : b1;
        const float (*sh_red)[OUT_DIM] = (eb == 0) ? sh_redA : sh_redB;

        // Finalize X[t]
        float X = 0.f;
#pragma unroll
        for (int gg = 0; gg < 32; ++gg)
            X += sh_red[gg][t];

        if (t < N_CAPS) shc[t] = 1.0f / N_CAPS;
        float logit_a = 0.f, logit_b = 0.f;
        __syncthreads();

        for (int iter = 0; iter < 3; ++iter) {
            // s_o = X * sum_n c_n W[n,o]  (column LDS)
            float s = 0.f;
#pragma unroll
            for (int n = 0; n < N_CAPS; ++n)
                s += shc[n] * sh_w[n * WROW + t];
            s *= X;

            float sq = s * s;
#pragma unroll
            for (int off = 16; off > 0; off >>= 1)
                sq += __shfl_xor_sync(0xffffffffu, sq, off);
            if (lane == 0) shred[t >> 5] = sq;
            shrp0[t] = s * X;            // pre-scale routed vector
            __syncthreads();

            float tot   = shred[0] + shred[1] + shred[2] + shred[3];
            float scale = sqrtf(tot) / (1.0f + tot);   // norm/(1+norm^2)

            if (iter == 2) {
                out[b * OUT_DIM + t] = scale * s;      // final squash
                break;
            }

            // logits partial: cap (t&63), o-half (t>>6); scale folded in
            {
                int n_id = t & 63, oh = t >> 6;
                const float4* wrow = reinterpret_cast<const float4*>(&sh_w[n_id * WROW]) + oh * 16;
                const float4* rp4  = reinterpret_cast<const float4*>(shrp0) + oh * 16;
                float acc = 0.f;
#pragma unroll
                for (int j = 0; j < 16; ++j) {
                    float4 w4v = wrow[j];
                    float4 r4v = rp4[j];
                    acc += w4v.x * r4v.x + w4v.y * r4v.y + w4v.z * r4v.z + w4v.w * r4v.w;
                }
                shpart[t] = scale * acc;
            }
            __syncthreads();

            if (t < 32) {
                logit_a += shpart[t]      + shpart[t + 64];
                logit_b += shpart[t + 32] + shpart[t + 96];
                float m = fmaxf(logit_a, logit_b);
#pragma unroll
                for (int off = 16; off > 0; off >>= 1)
                    m = fmaxf(m, __shfl_xor_sync(0xffffffffu, m, off));
                float ea = __expf(logit_a - m);
                float eb2 = __expf(logit_b - m);
                float sm = ea + eb2;
#pragma unroll
                for (int off = 16; off > 0; off >>= 1)
                    sm += __shfl_xor_sync(0xffffffffu, sm, off);
                float inv = 1.0f / sm;
                shc[t]      = ea * inv;
                shc[t + 32] = eb2 * inv;
            }
            __syncthreads();
        }
        __syncthreads();   // protect shc/shrp0 reuse across eb
    }
}

// ---------------------------------------------------------------------------
extern "C" void kernel_launch(void* const* d_in, const int* in_sizes, int n_in,
                              void* d_out, int out_size) {
    const float* x = (const float*)d_in[0];             // (1152, 256, 128)
    const float* w = (const float*)d_in[1];             // (64, 16, 128)
    float* out = (float*)d_out;                         // (256, 1, 128)

    capsule_fused<<<NBLK, THREADS>>>(reinterpret_cast<const float4*>(x),
                                     reinterpret_cast<const float4*>(w),
                                     out);
}